// round 1
// baseline (speedup 1.0000x reference)
#include <cuda_runtime.h>
#include <cuda_fp16.h>

// Problem constants
#define BN   128    // batch
#define DN   512    // inputs = hidden = outputs = maxlen
#define TN   512    // timesteps
#define NCTA 128
#define NTHR 256

// ---------------- device scratch (allowed: __device__ globals) ----------------
__device__ __align__(16) float  d_xT[(size_t)TN * DN * BN];     // [t][m][b] = x[b][m][t]   (134 MB)
__device__ __align__(16) __half d_x16[(size_t)BN * DN * TN];    // fp16 copy of x, [b][m][t] (67 MB)
__device__ __align__(16) float  d_hT[2][DN * BN];               // double-buffered h, [j][b]
__device__ __align__(16) float  d_logitsT[DN * BN];             // [j][b]
__device__ __align__(16) float  d_appliedT[DN * BN];            // [t'][b]
__device__ __align__(16) float  d_gT[DN * BN];                  // [j][b]
__device__ unsigned d_bar_count;
__device__ unsigned d_bar_sense;

// ---------------- init kernels ----------------
__global__ void k_init() {
    int i = blockIdx.x * blockDim.x + threadIdx.x;
    if (i < DN * BN) d_hT[0][i] = 0.0f;
    if (i == 0) { d_bar_count = 0u; d_bar_sense = 0u; }
}

// transpose x[b][m][t] -> xT[t][m][b]
__global__ void k_transpose(const float* __restrict__ x) {
    __shared__ float tile[32][33];
    int t0 = blockIdx.x * 32;           // 16 blocks
    int b0 = blockIdx.y * 32;           // 4 blocks
    int m  = blockIdx.z;                // 512 blocks
    int tx = threadIdx.x & 31;
    int ty = threadIdx.x >> 5;          // 0..7
    #pragma unroll
    for (int r = 0; r < 32; r += 8)
        tile[ty + r][tx] = x[(size_t)(b0 + ty + r) * DN * TN + (size_t)m * TN + (t0 + tx)];
    __syncthreads();
    #pragma unroll
    for (int r = 0; r < 32; r += 8)
        d_xT[(size_t)(t0 + ty + r) * (DN * BN / DN * DN) /* = 65536 */ + (size_t)m * BN + (b0 + tx)]
            = tile[tx][ty + r];
}

// fp32 -> fp16 copy of x
__global__ void k_tohalf(const float* __restrict__ x) {
    const float2* x2 = (const float2*)x;
    __half2* o2 = (__half2*)d_x16;
    size_t n2 = (size_t)BN * DN * TN / 2;
    for (size_t i = (size_t)blockIdx.x * blockDim.x + threadIdx.x; i < n2;
         i += (size_t)gridDim.x * blockDim.x) {
        o2[i] = __float22half2_rn(x2[i]);
    }
}

// ---------------- grid barrier (128 co-resident CTAs) ----------------
__device__ __forceinline__ void gridbar(unsigned& epoch) {
    __syncthreads();
    if (threadIdx.x == 0) {
        epoch += NCTA;
        __threadfence();
        unsigned a = atomicAdd(&d_bar_count, 1u) + 1u;
        if (a == epoch) {
            atomicExch(&d_bar_sense, epoch);
        } else {
            while (*(volatile unsigned*)&d_bar_sense < epoch) { }
        }
        __threadfence();
    }
    __syncthreads();
}

// ---------------- warp reductions ----------------
__device__ __forceinline__ float warpMax(float v) {
    #pragma unroll
    for (int o = 16; o; o >>= 1) v = fmaxf(v, __shfl_xor_sync(0xffffffffu, v, o));
    return v;
}
__device__ __forceinline__ float warpSum(float v) {
    #pragma unroll
    for (int o = 16; o; o >>= 1) v += __shfl_xor_sync(0xffffffffu, v, o);
    return v;
}

// ---------------- N-partitioned GEMM stage: 4 output cols per CTA ----------------
// out[b][j] = sum_k act[b][k] * W[j][k] + bias[j];  act stored transposed [k][b].
// act0 covers k in [0,512), act1 covers k in [512, 1024) (if KT==16).
// mode: 0 = plain -> outT[j][b], 1 = relu -> outT[j][b], 2 = plain -> out[b][j] (row-major)
__device__ __forceinline__ void gemm4(
    const float* __restrict__ act0, const float* __restrict__ act1,
    const float* __restrict__ W, int KT, const float* __restrict__ bias,
    float* __restrict__ outp, int c, int mode, float* s_act, float* s_w)
{
    const int b  = threadIdx.x & 127;
    const int jj = threadIdx.x >> 7;     // 0..1
    const int j0 = c * 4 + jj * 2;
    const int Ktot = KT * 64;
    float acc0 = 0.0f, acc1 = 0.0f;
    for (int tile = 0; tile < KT; ++tile) {
        const int kbase = tile * 64;
        const float* src = (kbase < 512) ? (act0 + (size_t)kbase * BN)
                                         : (act1 + (size_t)(kbase - 512) * BN);
        __syncthreads();
        {   // load 64x128 activation tile (32 KB), coalesced float4
            const float4* s4 = (const float4*)src;
            float4* dst = (float4*)s_act;
            #pragma unroll
            for (int i = 0; i < 8; ++i) dst[threadIdx.x + i * NTHR] = s4[threadIdx.x + i * NTHR];
        }
        {   // 4 cols x 64 k weights = 256 floats, one per thread
            int i = threadIdx.x;
            int jc = i >> 6, k = i & 63;
            s_w[i] = W[(size_t)(c * 4 + jc) * Ktot + kbase + k];
        }
        __syncthreads();
        const float* wa = s_w + (jj * 2) * 64;
        const float* wb = wa + 64;
        #pragma unroll 16
        for (int k = 0; k < 64; ++k) {
            float a = s_act[k * BN + b];
            acc0 = fmaf(a, wa[k], acc0);
            acc1 = fmaf(a, wb[k], acc1);
        }
    }
    acc0 += bias[j0];
    acc1 += bias[j0 + 1];
    if (mode == 1) { acc0 = fmaxf(acc0, 0.0f); acc1 = fmaxf(acc1, 0.0f); }
    if (mode == 2) {
        outp[(size_t)b * DN + j0]     = acc0;
        outp[(size_t)b * DN + j0 + 1] = acc1;
    } else {
        outp[(size_t)j0 * BN + b]       = acc0;
        outp[(size_t)(j0 + 1) * BN + b] = acc1;
    }
}

// ---------------- stage B: softmax + einsum, CTA handles batch b ----------------
__device__ __forceinline__ void stageB(int b, float* s_vec, float* s_scr, float* s_red) {
    const int tid = threadIdx.x;
    // gather logits row b (512 values, 2 per thread)
    float l0 = d_logitsT[(size_t)tid * BN + b];
    float l1 = d_logitsT[(size_t)(tid + 256) * BN + b];
    float vmax = warpMax(fmaxf(l0, l1));
    if ((tid & 31) == 0) s_scr[tid >> 5] = vmax;
    __syncthreads();
    float M = s_scr[0];
    #pragma unroll
    for (int i = 1; i < 8; ++i) M = fmaxf(M, s_scr[i]);
    float e0 = __expf(l0 - M), e1 = __expf(l1 - M);
    float ws = warpSum(e0 + e1);
    __syncthreads();
    if ((tid & 31) == 0) s_scr[tid >> 5] = ws;
    __syncthreads();
    float S = 0.0f;
    #pragma unroll
    for (int i = 0; i < 8; ++i) S += s_scr[i];
    float inv = 1.0f / S;
    s_vec[tid] = e0 * inv;
    s_vec[tid + 256] = e1 * inv;
    __syncthreads();

    // einsum: applied[b][t'] = sum_m w[m] * x16[b][m][t']
    const int mq = tid >> 6;     // 0..3 : quarter of m
    const int tg = tid & 63;     // 8 t'-cols per thread
    float acc[8] = {0, 0, 0, 0, 0, 0, 0, 0};
    const __half* xb = d_x16 + (size_t)b * DN * TN;
    for (int mi = 0; mi < 128; ++mi) {
        int m_ = mq * 128 + mi;
        float w = s_vec[m_];
        uint4 v = *(const uint4*)(xb + (size_t)m_ * TN + tg * 8);
        const __half2* h2 = (const __half2*)&v;
        float2 f0 = __half22float2(h2[0]);
        float2 f1 = __half22float2(h2[1]);
        float2 f2 = __half22float2(h2[2]);
        float2 f3 = __half22float2(h2[3]);
        acc[0] = fmaf(w, f0.x, acc[0]); acc[1] = fmaf(w, f0.y, acc[1]);
        acc[2] = fmaf(w, f1.x, acc[2]); acc[3] = fmaf(w, f1.y, acc[3]);
        acc[4] = fmaf(w, f2.x, acc[4]); acc[5] = fmaf(w, f2.y, acc[5]);
        acc[6] = fmaf(w, f3.x, acc[6]); acc[7] = fmaf(w, f3.y, acc[7]);
    }
    #pragma unroll
    for (int q = 0; q < 8; ++q) s_red[mq * DN + tg * 8 + q] = acc[q];
    __syncthreads();
    for (int col = tid; col < DN; col += NTHR) {
        float v = s_red[col] + s_red[DN + col] + s_red[2 * DN + col] + s_red[3 * DN + col];
        d_appliedT[(size_t)col * BN + b] = v;
    }
}

// ---------------- stage D: gi/gh GEMMs + GRU, CTA owns 4 hidden cols ----------------
__device__ __forceinline__ void stageD(
    const float* __restrict__ hTold, float* __restrict__ hTnew,
    const float* __restrict__ w_ih, const float* __restrict__ w_hh,
    const float* __restrict__ b_ih, const float* __restrict__ b_hh,
    int c, float* s_act, float* s_w)
{
    const int b  = threadIdx.x & 127;
    const int jj = threadIdx.x >> 7;
    const int j0 = c * 4 + jj * 2;
    float gi[6] = {0, 0, 0, 0, 0, 0};   // [gate*2 + col]
    float gh[6] = {0, 0, 0, 0, 0, 0};
    for (int pass = 0; pass < 2; ++pass) {
        const float* act = pass ? hTold : d_gT;
        const float* W   = pass ? w_hh : w_ih;
        float* acc = pass ? gh : gi;
        for (int tile = 0; tile < 8; ++tile) {
            __syncthreads();
            {
                const float4* s4 = (const float4*)(act + (size_t)tile * 64 * BN);
                float4* dst = (float4*)s_act;
                #pragma unroll
                for (int i = 0; i < 8; ++i) dst[threadIdx.x + i * NTHR] = s4[threadIdx.x + i * NTHR];
            }
            // 3 gates x 4 cols x 64 k = 768 floats
            for (int i = threadIdx.x; i < 768; i += NTHR) {
                int gjc = i >> 6, k = i & 63;
                int gate = gjc >> 2, jc = gjc & 3;
                s_w[i] = W[(size_t)(gate * DN + c * 4 + jc) * DN + tile * 64 + k];
            }
            __syncthreads();
            const int o0 = (jj * 2) * 64;
            #pragma unroll 8
            for (int k = 0; k < 64; ++k) {
                float a = s_act[k * BN + b];
                acc[0] = fmaf(a, s_w[o0 + k],            acc[0]);
                acc[1] = fmaf(a, s_w[o0 + 64 + k],       acc[1]);
                acc[2] = fmaf(a, s_w[o0 + 256 + k],      acc[2]);
                acc[3] = fmaf(a, s_w[o0 + 320 + k],      acc[3]);
                acc[4] = fmaf(a, s_w[o0 + 512 + k],      acc[4]);
                acc[5] = fmaf(a, s_w[o0 + 576 + k],      acc[5]);
            }
        }
    }
    #pragma unroll
    for (int cc = 0; cc < 2; ++cc) {
        int j = j0 + cc;
        float ir = gi[0 + cc] + b_ih[j];
        float iz = gi[2 + cc] + b_ih[DN + j];
        float in_ = gi[4 + cc] + b_ih[2 * DN + j];
        float hr = gh[0 + cc] + b_hh[j];
        float hz = gh[2 + cc] + b_hh[DN + j];
        float hn = gh[4 + cc] + b_hh[2 * DN + j];
        float r = 1.0f / (1.0f + __expf(-(ir + hr)));
        float z = 1.0f / (1.0f + __expf(-(iz + hz)));
        float n = tanhf(in_ + r * hn);
        float hold = hTold[(size_t)j * BN + b];
        hTnew[(size_t)j * BN + b] = (1.0f - z) * n + z * hold;
    }
}

// ---------------- persistent kernel ----------------
__global__ void __launch_bounds__(NTHR, 1) rnn_persistent(
    const float* __restrict__ x,
    const float* __restrict__ attn_W, const float* __restrict__ attn_b,
    const float* __restrict__ comb_W, const float* __restrict__ comb_b,
    const float* __restrict__ w_ih, const float* __restrict__ w_hh,
    const float* __restrict__ b_ih, const float* __restrict__ b_hh,
    const float* __restrict__ out_W, const float* __restrict__ out_b,
    float* __restrict__ out)
{
    __shared__ float s_act[64 * BN];      // 32 KB (also reused as reduce buffer in stage B)
    __shared__ float s_w[12 * 64];        // 3 KB
    __shared__ float s_vec[DN + 64];      // softmax weights + scratch

    const int c = blockIdx.x;             // 0..127
    unsigned epoch = 0;

    for (int t = 0; t < TN; ++t) {
        const float* hOld = d_hT[t & 1];
        float* hNew = d_hT[(t + 1) & 1];
        const float* inpT = d_xT + (size_t)t * (DN * BN / DN * DN); // t * 65536

        // A: logits = [inp | h] @ attn_W.T + attn_b
        gemm4(inpT, hOld, attn_W, 16, attn_b, d_logitsT, c, 0, s_act, s_w);
        gridbar(epoch);
        // B: softmax + einsum
        stageB(c, s_vec, s_vec + DN, s_act);
        gridbar(epoch);
        // C: g = relu([inp | applied] @ comb_W.T + comb_b)
        gemm4(inpT, d_appliedT, comb_W, 16, comb_b, d_gT, c, 1, s_act, s_w);
        gridbar(epoch);
        // D: gi/gh GEMMs + GRU -> hNew
        stageD(hOld, hNew, w_ih, w_hh, b_ih, b_hh, c, s_act, s_w);
        gridbar(epoch);
    }
    // final: out = h @ out_W.T + out_b ; final h is in buffer 0
    gemm4(d_hT[0], d_hT[0], out_W, 8, out_b, out, c, 2, s_act, s_w);
}

// ---------------- launch ----------------
extern "C" void kernel_launch(void* const* d_in, const int* in_sizes, int n_in,
                              void* d_out, int out_size) {
    (void)in_sizes; (void)n_in; (void)out_size;
    const float* x      = (const float*)d_in[0];
    const float* attn_W = (const float*)d_in[1];
    const float* attn_b = (const float*)d_in[2];
    const float* comb_W = (const float*)d_in[3];
    const float* comb_b = (const float*)d_in[4];
    const float* w_ih   = (const float*)d_in[5];
    const float* w_hh   = (const float*)d_in[6];
    const float* b_ih   = (const float*)d_in[7];
    const float* b_hh   = (const float*)d_in[8];
    const float* out_W  = (const float*)d_in[9];
    const float* out_b  = (const float*)d_in[10];
    float* out = (float*)d_out;

    k_init<<<(DN * BN + NTHR - 1) / NTHR, NTHR>>>();
    k_transpose<<<dim3(16, 4, 512), NTHR>>>(x);
    k_tohalf<<<4096, NTHR>>>(x);
    rnn_persistent<<<NCTA, NTHR>>>(x, attn_W, attn_b, comb_W, comb_b,
                                   w_ih, w_hh, b_ih, b_hh, out_W, out_b, out);
}